// round 15
// baseline (speedup 1.0000x reference)
#include <cuda_runtime.h>
#include <cuda_bf16.h>
#include <math.h>

#define S_LEN  512
#define BATCH  4
#define NHEAD  16
#define BH     (BATCH * NHEAD)
#define DHEAD  64
#define DMODEL 1024
#define D3     3072
#define NTOK   2048   // BATCH * S_LEN

typedef unsigned long long u64;

// ---------------- bf16 mma helper (m16n8k16, verified layout) ----------------
__device__ __forceinline__ void mma_bf16(float* c, const unsigned* a, const unsigned* b) {
    asm volatile("mma.sync.aligned.m16n8k16.row.col.f32.bf16.bf16.f32 "
        "{%0,%1,%2,%3}, {%4,%5,%6,%7}, {%8,%9}, {%0,%1,%2,%3};"
        : "+f"(c[0]), "+f"(c[1]), "+f"(c[2]), "+f"(c[3])
        : "r"(a[0]), "r"(a[1]), "r"(a[2]), "r"(a[3]), "r"(b[0]), "r"(b[1]));
}

// split fp32 pair (a,b) into packed bf16 hi word + bf16 lo (residual) word
__device__ __forceinline__ void split_pair(float a, float b, unsigned& H, unsigned& L) {
    __nv_bfloat162 h2 = __floats2bfloat162_rn(a, b);
    float ra = a - __bfloat162float(h2.x);
    float rb = b - __bfloat162float(h2.y);
    __nv_bfloat162 l2 = __floats2bfloat162_rn(ra, rb);
    H = *(unsigned*)&h2;
    L = *(unsigned*)&l2;
}

// ---------------- scratch (static device globals; no allocation) ----------------
__device__ float g_qkv_r[NTOK * D3];       // 25.2 MB
__device__ float g_qkv_i[NTOK * D3];
__device__ float g_rc[S_LEN * DHEAD];
__device__ float g_rs[S_LEN * DHEAD];
// pre-split operands: packed bf16 H/L pair-words, row-major [row][K/2 words]
__device__ unsigned g_xRH[NTOK * 512],  g_xRL[NTOK * 512];
__device__ unsigned g_xIH[NTOK * 512],  g_xIL[NTOK * 512];
__device__ unsigned g_wqRH[D3 * 512],   g_wqRL[D3 * 512];
__device__ unsigned g_wqIH[D3 * 512],   g_wqIL[D3 * 512];
__device__ unsigned g_woRH[DMODEL * 512], g_woRL[DMODEL * 512];
__device__ unsigned g_woIH[DMODEL * 512], g_woIL[DMODEL * 512];
__device__ unsigned g_aoRH[NTOK * 512], g_aoRL[NTOK * 512];   // attn out (pre-split)
__device__ unsigned g_aoIH[NTOK * 512], g_aoIL[NTOK * 512];
// rotated K, bf16 H/L packed pairs, layout [bh][s][d-pair word] (B-frag ready)
__device__ unsigned g_kbrH[BH * 512 * 32], g_kbrL[BH * 512 * 32];
__device__ unsigned g_kbiH[BH * 512 * 32], g_kbiL[BH * 512 * 32];
// V transposed, bf16 H/L packed pairs, layout [bh][d][s-pair word] (B-frag ready)
__device__ unsigned g_vtrH[BH * 64 * 256], g_vtrL[BH * 64 * 256];
__device__ unsigned g_vtiH[BH * 64 * 256], g_vtiL[BH * 64 * 256];

// ---------------- RoPE rotor table ----------------
__global__ void rope_table_kernel() {
    int s = blockIdx.x, d = threadIdx.x;
    float inv = powf(10000.0f, -((float)d) / 64.0f);
    float ang = (float)s * inv;
    g_rc[s * DHEAD + d] = cosf(ang);
    g_rs[s * DHEAD + d] = sinf(ang);
}

// ---------------- fp32 -> bf16 H/L pack (float4 per thread) ----------------
__global__ __launch_bounds__(256)
void pack_kernel(const float* __restrict__ src,
                 unsigned* __restrict__ H, unsigned* __restrict__ L)
{
    int i = blockIdx.x * 256 + threadIdx.x;   // word-pair index
    float4 v = ((const float4*)src)[i];
    uint2 h, l;
    split_pair(v.x, v.y, h.x, l.x);
    split_pair(v.z, v.w, h.y, l.y);
    ((uint2*)H)[i] = h;
    ((uint2*)L)[i] = l;
}

// ======= complex GEMM, pre-split bf16 H/L inputs: C = A * B^T =======
// R13 memory structure; MMA phase reordered into 12 passes of 8 independent
// chains (accR / accR2 / accI banks; accR2 holds +Ai*Bi, subtracted at end).
#define SSTW 12
__global__ __launch_bounds__(128)
void cgemm_pk_kernel(const unsigned* __restrict__ aRH, const unsigned* __restrict__ aRL,
                     const unsigned* __restrict__ aIH, const unsigned* __restrict__ aIL,
                     const unsigned* __restrict__ bRH, const unsigned* __restrict__ bRL,
                     const unsigned* __restrict__ bIH, const unsigned* __restrict__ bIL,
                     float* __restrict__ Cr, float* __restrict__ Ci,
                     int N, int Kw /* K/2 words per row */)
{
    __shared__ unsigned sRH[64 * SSTW], sRL[64 * SSTW];
    __shared__ unsigned sIH[64 * SSTW], sIL[64 * SSTW];
    __shared__ unsigned tRH[64 * SSTW], tRL[64 * SSTW];
    __shared__ unsigned tIH[64 * SSTW], tIL[64 * SSTW];

    int tid  = threadIdx.x;
    int lane = tid & 31, warp = tid >> 5;
    int wm = (warp & 1) * 32;
    int wn = (warp >> 1) * 32;
    int g = lane >> 2, t = lane & 3;
    int m0 = blockIdx.y * 64;
    int n0 = blockIdx.x * 64;

    int lrow = tid >> 1;
    int half = tid & 1;
    int so = lrow * SSTW + half * 4;
    size_t srcA = (size_t)(m0 + lrow) * Kw + half * 4;
    size_t srcB = (size_t)(n0 + lrow) * Kw + half * 4;

    float accR[8][4], accR2[8][4], accI[8][4];
#pragma unroll
    for (int p = 0; p < 8; p++)
#pragma unroll
        for (int j = 0; j < 4; j++) {
            accR[p][j] = 0.f; accR2[p][j] = 0.f; accI[p][j] = 0.f;
        }

    int NK = Kw / 8;
    for (int kt = 0; kt < NK; kt++) {
        size_t ko = (size_t)kt * 8;
        // global loads issued early (overlap previous tile's MMA phase)
        uint4 vaRH = *(const uint4*)(aRH + srcA + ko);
        uint4 vaRL = *(const uint4*)(aRL + srcA + ko);
        uint4 vaIH = *(const uint4*)(aIH + srcA + ko);
        uint4 vaIL = *(const uint4*)(aIL + srcA + ko);
        uint4 vbRH = *(const uint4*)(bRH + srcB + ko);
        uint4 vbRL = *(const uint4*)(bRL + srcB + ko);
        uint4 vbIH = *(const uint4*)(bIH + srcB + ko);
        uint4 vbIL = *(const uint4*)(bIL + srcB + ko);

        __syncthreads();   // previous iter's frag reads done

        *(uint4*)(sRH + so) = vaRH;  *(uint4*)(sRL + so) = vaRL;
        *(uint4*)(sIH + so) = vaIH;  *(uint4*)(sIL + so) = vaIL;
        *(uint4*)(tRH + so) = vbRH;  *(uint4*)(tRL + so) = vbRL;
        *(uint4*)(tIH + so) = vbIH;  *(uint4*)(tIL + so) = vbIL;

        __syncthreads();

        // A fragments (stride 12, conflict-free, verified since R7)
        unsigned fRH[2][4], fRL[2][4], fIH[2][4], fIL[2][4];
#pragma unroll
        for (int mt = 0; mt < 2; mt++) {
            int r0 = (wm + mt * 16 + g) * SSTW + t;
            int r1 = r0 + 8 * SSTW;
            fRH[mt][0] = sRH[r0]; fRH[mt][1] = sRH[r1];
            fRH[mt][2] = sRH[r0 + 4]; fRH[mt][3] = sRH[r1 + 4];
            fRL[mt][0] = sRL[r0]; fRL[mt][1] = sRL[r1];
            fRL[mt][2] = sRL[r0 + 4]; fRL[mt][3] = sRL[r1 + 4];
            fIH[mt][0] = sIH[r0]; fIH[mt][1] = sIH[r1];
            fIH[mt][2] = sIH[r0 + 4]; fIH[mt][3] = sIH[r1 + 4];
            fIL[mt][0] = sIL[r0]; fIL[mt][1] = sIL[r1];
            fIL[mt][2] = sIL[r0 + 4]; fIL[mt][3] = sIL[r1 + 4];
        }

        // B fragments, all 4 n-tiles staged
        unsigned brH[4][2], brL[4][2], biH[4][2], biL[4][2];
#pragma unroll
        for (int nt = 0; nt < 4; nt++) {
            int rb = (wn + nt * 8 + g) * SSTW + t;
            brH[nt][0] = tRH[rb]; brH[nt][1] = tRH[rb + 4];
            brL[nt][0] = tRL[rb]; brL[nt][1] = tRL[rb + 4];
            biH[nt][0] = tIH[rb]; biH[nt][1] = tIH[rb + 4];
            biL[nt][0] = tIL[rb]; biL[nt][1] = tIL[rb + 4];
        }

        // 12 passes x 8 independent MMAs (same-chain reuse distance = 8)
#define GP(ACC, AF, BF)                                             \
        _Pragma("unroll") for (int nt = 0; nt < 4; nt++)            \
        _Pragma("unroll") for (int mt = 0; mt < 2; mt++)            \
            mma_bf16(ACC[mt * 4 + nt], AF[mt], BF[nt]);
        GP(accR,  fRH, brH)
        GP(accI,  fRH, biH)
        GP(accR2, fIH, biH)
        GP(accI,  fIH, brH)
        GP(accR,  fRH, brL)
        GP(accI,  fRH, biL)
        GP(accR2, fIH, biL)
        GP(accI,  fIH, brL)
        GP(accR,  fRL, brH)
        GP(accI,  fRL, biH)
        GP(accR2, fIL, biH)
        GP(accI,  fIL, brH)
#undef GP
    }

    // epilogue: re = accR - accR2
#pragma unroll
    for (int mt = 0; mt < 2; mt++)
#pragma unroll
        for (int nt = 0; nt < 4; nt++) {
            int p = mt * 4 + nt;
            int m = m0 + wm + mt * 16 + g;
            int n = n0 + wn + nt * 8 + t * 2;
            size_t c0 = (size_t)m * N + n;
            size_t c1 = (size_t)(m + 8) * N + n;
            *(float2*)(Cr + c0) = make_float2(accR[p][0] - accR2[p][0],
                                              accR[p][1] - accR2[p][1]);
            *(float2*)(Cr + c1) = make_float2(accR[p][2] - accR2[p][2],
                                              accR[p][3] - accR2[p][3]);
            *(float2*)(Ci + c0) = make_float2(accI[p][0], accI[p][1]);
            *(float2*)(Ci + c1) = make_float2(accI[p][2], accI[p][3]);
        }
}

// ---------- K: rotate + split to bf16 H/L pairs, layout [bh][s][d-pair] ----------
__global__ __launch_bounds__(256)
void kpack_kernel(const float* __restrict__ qkv_r, const float* __restrict__ qkv_i)
{
    int bh = blockIdx.y;
    int b = bh >> 4, h = bh & 15;
    int id = blockIdx.x * 256 + threadIdx.x;   // 0..16383 = s*32 + wd
    int s = id >> 5, wd = id & 31;
    int d = 2 * wd;
    size_t off = ((size_t)b * S_LEN + s) * D3 + DMODEL + (size_t)h * DHEAD + d;
    float2 kr = *(const float2*)(qkv_r + off);
    float2 ki = *(const float2*)(qkv_i + off);
    float2 co = *(const float2*)(g_rc + s * DHEAD + d);
    float2 si = *(const float2*)(g_rs + s * DHEAD + d);
    float r0 = kr.x * co.x - ki.x * si.x;
    float i0 = kr.x * si.x + ki.x * co.x;
    float r1 = kr.y * co.y - ki.y * si.y;
    float i1 = kr.y * si.y + ki.y * co.y;
    size_t o = (size_t)bh * 16384 + id;
    unsigned H, L;
    split_pair(r0, r1, H, L); g_kbrH[o] = H; g_kbrL[o] = L;
    split_pair(i0, i1, H, L); g_kbiH[o] = H; g_kbiL[o] = L;
}

// ---------- V: transpose + split to bf16 H/L pairs, layout [bh][d][s-pair] ----------
__global__ __launch_bounds__(256)
void vpack_kernel(const float* __restrict__ qkv_r, const float* __restrict__ qkv_i)
{
    __shared__ float sVr[64][65], sVi[64][65];
    int sc = blockIdx.x;       // s-chunk of 64
    int bh = blockIdx.y;
    int b = bh >> 4, h = bh & 15;
    int tid = threadIdx.x;

#pragma unroll
    for (int i = 0; i < 16; i++) {
        int id = i * 256 + tid;        // 0..4095 = sl*64 + d
        int sl = id >> 6, d = id & 63;
        size_t off = ((size_t)b * S_LEN + sc * 64 + sl) * D3 + 2 * DMODEL
                   + (size_t)h * DHEAD + d;
        sVr[sl][d] = qkv_r[off];
        sVi[sl][d] = qkv_i[off];
    }
    __syncthreads();

#pragma unroll
    for (int i = 0; i < 8; i++) {
        int id = i * 256 + tid;        // 0..2047 = d*32 + ws
        int d = id >> 5, ws = id & 31;
        size_t o = ((size_t)bh * 64 + d) * 256 + sc * 32 + ws;
        unsigned H, L;
        split_pair(sVr[2 * ws][d], sVr[2 * ws + 1][d], H, L);
        g_vtrH[o] = H; g_vtrL[o] = L;
        split_pair(sVi[2 * ws][d], sVi[2 * ws + 1][d], H, L);
        g_vtiH[o] = H; g_vtiL[o] = L;
    }
}

// ========== fused attention, all-MMA: one block per (b, h, 16-q tile) ==========
#define OFF_QRH 0
#define OFF_QRL 576
#define OFF_QIH 1152
#define OFF_QIL 1728
#define OFF_WC  2304
#define OFF_WS  10528
#define OFF_WCH 18752
#define OFF_WCL 22912
#define OFF_WSH 27072
#define OFF_WSL 31232
#define ATTN_SMEM_WORDS 35392
#define ATTN_SMEM (ATTN_SMEM_WORDS * 4)

__global__ __launch_bounds__(256)
void attn_kernel(const float* __restrict__ qkv_r, const float* __restrict__ qkv_i)
{
    extern __shared__ unsigned sm[];
    unsigned* sQrH = sm + OFF_QRH;
    unsigned* sQrL = sm + OFF_QRL;
    unsigned* sQiH = sm + OFF_QIH;
    unsigned* sQiL = sm + OFF_QIL;
    float* sWc = (float*)(sm + OFF_WC);
    float* sWs = (float*)(sm + OFF_WS);
    unsigned* sWcH = sm + OFF_WCH;
    unsigned* sWcL = sm + OFF_WCL;
    unsigned* sWsH = sm + OFF_WSH;
    unsigned* sWsL = sm + OFF_WSL;

    int tid = threadIdx.x;
    int w = tid >> 5, l = tid & 31;
    int g = l >> 2, t = l & 3;
    int h = blockIdx.y, b = blockIdx.z;
    int bh = b * NHEAD + h;
    int q0 = blockIdx.x * 16;
    const size_t tok = (size_t)b * S_LEN;

    // ---- Q: load + rotate + split, word layout [q][d-pair] stride 36 ----
#pragma unroll
    for (int i = 0; i < 2; i++) {
        int id = tid + 256 * i;        // 0..511 = q*32 + wd
        int q = id >> 5, wd = id & 31;
        int s = q0 + q;
        int d = 2 * wd;
        size_t off = (tok + s) * D3 + (size_t)h * DHEAD + d;
        float2 qr = *(const float2*)(qkv_r + off);
        float2 qi = *(const float2*)(qkv_i + off);
        float2 co = *(const float2*)(g_rc + s * DHEAD + d);
        float2 si = *(const float2*)(g_rs + s * DHEAD + d);
        float r0 = qr.x * co.x - qi.x * si.x;
        float i0 = qr.x * si.x + qi.x * co.x;
        float r1 = qr.y * co.y - qi.y * si.y;
        float i1 = qr.y * si.y + qi.y * co.y;
        unsigned H, L;
        split_pair(r0, r1, H, L); sQrH[q * 36 + wd] = H; sQrL[q * 36 + wd] = L;
        split_pair(i0, i1, H, L); sQiH[q * 36 + wd] = H; sQiL[q * 36 + wd] = L;
    }
    __syncthreads();

    // ---- scores MMA: warp w owns k-rows [64w, 64w+64); nt processed in pairs ----
    {
        float accR[8][4], accI[8][4];
#pragma unroll
        for (int p = 0; p < 8; p++)
#pragma unroll
            for (int j = 0; j < 4; j++) { accR[p][j] = 0.f; accI[p][j] = 0.f; }

        const size_t kbase = (size_t)bh * 16384;
#pragma unroll
        for (int ks = 0; ks < 4; ks++) {
            int r0 = g * 36 + ks * 8 + t;
            int r1 = (g + 8) * 36 + ks * 8 + t;
            unsigned aQrH[4] = {sQrH[r0], sQrH[r1], sQrH[r0 + 4], sQrH[r1 + 4]};
            unsigned aQrL[4] = {sQrL[r0], sQrL[r1], sQrL[r0 + 4], sQrL[r1 + 4]};
            unsigned aQiH[4] = {sQiH[r0], sQiH[r1], sQiH[r0 + 4], sQiH[r1 + 4]};
            unsigned aQiL[4] = {sQiL[r0], sQiL[r1], sQiL[r0 + 4], sQiL[r1 + 4]};
            unsigned nQrH[4], nQrL[4];
#pragma unroll
            for (int j = 0; j < 4; j++) {
                nQrH[j] = aQrH[j] ^ 0x80008000u;
                nQrL[j] = aQrL[j] ^ 0x80008000u;
            }
#pragma unroll
            for (int np = 0; np < 4; np++) {
                // two n-tiles a,b -> 4 interleaved chains (distance 4)
                unsigned krH[2][2], krL[2][2], kiH[2][2], kiL[2][2];
#pragma unroll
                for (int u = 0; u < 2; u++) {
                    int srow = w * 64 + (2 * np + u) * 8 + g;
                    size_t kb = kbase + (size_t)srow * 32 + ks * 8 + t;
                    krH[u][0] = g_kbrH[kb]; krH[u][1] = g_kbrH[kb + 4];
                    krL[u][0] = g_kbrL[kb]; krL[u][1] = g_kbrL[kb + 4];
                    kiH[u][0] = g_kbiH[kb]; kiH[u][1] = g_kbiH[kb + 4];
                    kiL[u][0] = g_kbiL[kb]; kiL[u][1] = g_kbiL[kb + 4];
                }
                int pa = 2 * np, pb = 2 * np + 1;
                mma_bf16(accR[pa], aQrH, krH[0]); mma_bf16(accR[pb], aQrH, krH[1]);
                mma_bf16(accI[pa], aQiH, krH[0]); mma_bf16(accI[pb], aQiH, krH[1]);
                mma_bf16(accR[pa], aQiH, kiH[0]); mma_bf16(accR[pb], aQiH, kiH[1]);
                mma_bf16(accI[pa], nQrH, kiH[0]); mma_bf16(accI[pb], nQrH, kiH[1]);
                mma_bf16(accR[pa], aQrH, krL[0]); mma_bf16(accR[pb], aQrH, krL[1]);
                mma_bf16(accI[pa], aQiH, krL[0]); mma_bf16(accI[pb], aQiH, krL[1]);
                mma_bf16(accR[pa], aQrL, krH[0]); mma_bf16(accR[pb], aQrL, krH[1]);
                mma_bf16(accI[pa], aQiL, krH[0]); mma_bf16(accI[pb], aQiL, krH[1]);
                mma_bf16(accR[pa], aQiH, kiL[0]); mma_bf16(accR[pb], aQiH, kiL[1]);
                mma_bf16(accI[pa], nQrH, kiL[0]); mma_bf16(accI[pb], nQrH, kiL[1]);
                mma_bf16(accR[pa], aQiL, kiH[0]); mma_bf16(accR[pb], aQiL, kiH[1]);
                mma_bf16(accI[pa], nQrL, kiH[0]); mma_bf16(accI[pb], nQrL, kiH[1]);
            }
        }

        const float scale = 0.125f;   // 1/sqrt(64)
#pragma unroll
        for (int nt = 0; nt < 8; nt++) {
            int col = w * 64 + nt * 8 + 2 * t;
            *(float2*)&sWc[g * 514 + col] =
                make_float2(accR[nt][0] * scale, accR[nt][1] * scale);
            *(float2*)&sWc[(g + 8) * 514 + col] =
                make_float2(accR[nt][2] * scale, accR[nt][3] * scale);
            *(float2*)&sWs[g * 514 + col] =
                make_float2(accI[nt][0] * scale, accI[nt][1] * scale);
            *(float2*)&sWs[(g + 8) * 514 + col] =
                make_float2(accI[nt][2] * scale, accI[nt][3] * scale);
        }
    }
    __syncthreads();

    // ---- softmax + complex weights (bf16 H/L split): warp w -> rows w, w+8 ----
#pragma unroll
    for (int rr = 0; rr < 2; rr++) {
        int row = w + rr * 8;
        float* rc_ = sWc + row * 514;
        float* rs_ = sWs + row * 514;

        float mx = -1e30f;
#pragma unroll
        for (int j = 0; j < 16; j++) mx = fmaxf(mx, rc_[l + 32 * j]);
#pragma unroll
        for (int o = 16; o > 0; o >>= 1)
            mx = fmaxf(mx, __shfl_xor_sync(0xffffffff, mx, o));

        float sum = 0.f;
#pragma unroll
        for (int j = 0; j < 16; j++) {
            int idx = l + 32 * j;
            float e = __expf(rc_[idx] - mx);
            rc_[idx] = e;
            sum += e;
        }
#pragma unroll
        for (int o = 16; o > 0; o >>= 1)
            sum += __shfl_xor_sync(0xffffffff, sum, o);
        float inv = 1.0f / sum;

#pragma unroll
        for (int j = 0; j < 8; j++) {
            int k0 = 2 * l + 64 * j;
            int wd = l + 32 * j;
            float p0 = rc_[k0] * inv, p1 = rc_[k0 + 1] * inv;
            float s0, c0, s1, c1;
            sincosf(rs_[k0], &s0, &c0);
            sincosf(rs_[k0 + 1], &s1, &c1);
            unsigned H, L;
            split_pair(p0 * c0, p1 * c1, H, L);
            sWcH[row * 260 + wd] = H; sWcL[row * 260 + wd] = L;
            split_pair(p0 * s0, p1 * s1, H, L);
            sWsH[row * 260 + wd] = H; sWsL[row * 260 + wd] = L;
        }
    }
    __syncthreads();

    // ---- AV MMA: warp w -> d-cols [8w, 8w+8); 2 k-steps at once (4 chains) ----
    {
        float oR[2][4], oI[2][4];
#pragma unroll
        for (int u = 0; u < 2; u++)
#pragma unroll
            for (int j = 0; j < 4; j++) { oR[u][j] = 0.f; oI[u][j] = 0.f; }

        const size_t vbase = ((size_t)bh * 64 + 8 * w + g) * 256;
#pragma unroll 2
        for (int ks2 = 0; ks2 < 16; ks2++) {
            unsigned wcH[2][4], wcL[2][4], wsH[2][4], wsL[2][4];
            unsigned nsH[2][4], nsL[2][4];
            unsigned vrH[2][2], vrL[2][2], viH[2][2], viL[2][2];
#pragma unroll
            for (int u = 0; u < 2; u++) {
                int ks = 2 * ks2 + u;
                int r0 = g * 260 + ks * 8 + t;
                int r1 = (g + 8) * 260 + ks * 8 + t;
                wcH[u][0] = sWcH[r0]; wcH[u][1] = sWcH[r1];
                wcH[u][2] = sWcH[r0 + 4]; wcH[u][3] = sWcH[r1 + 4];
                wcL[u][0] = sWcL[r0]; wcL[u][1] = sWcL[r1];
                wcL[u][2] = sWcL[r0 + 4]; wcL[u][3] = sWcL[r1 + 4];
                wsH[u][0] = sWsH[r0]; wsH[u][1] = sWsH[r1];
                wsH[u][2] = sWsH[r0 + 4]; wsH[u][3] = sWsH[r1 + 4];
                wsL[u][0] = sWsL[r0]; wsL[u][1] = sWsL[r1];
                wsL[u][2] = sWsL[r0 + 4]; wsL[u][3] = sWsL[r1 + 4];
#pragma unroll
                for (int j = 0; j < 4; j++) {
                    nsH[u][j] = wsH[u][j] ^ 0x80008000u;
                    nsL[u][j] = wsL[u][j] ^ 0x80008000u;
                }
                size_t vb = vbase + ks * 8 + t;
                vrH[u][0] = g_vtrH[vb]; vrH[u][1] = g_vtrH[vb + 4];
                vrL[u][0] = g_vtrL[vb]; vrL[u][1] = g_vtrL[vb + 4];
                viH[u][0] = g_vtiH[vb]; viH[u][1] = g_vtiH[vb + 4];
                viL[u][0] = g_vtiL[vb]; viL[u][1] = g_vtiL[vb + 4];
            }
            // 6 groups x 4 independent chains
            mma_bf16(oR[0], wcH[0], vrH[0]); mma_bf16(oR[1], wcH[1], vrH[1]);
            mma_bf16(oI[0], wcH[0], viH[0]); mma_bf16(oI[1], wcH[1], viH[1]);
            mma_bf16(oR[0], nsH[0], viH[0]); mma_bf16(oR[1], nsH[1], viH[1]);
            mma_bf16(oI[0], wsH[0], vrH[0]); mma_bf16(oI[1], wsH[1], vrH[1]);
            mma_bf16(oR[0], wcH[0], vrL[0]); mma_bf16(oR[1], wcH[1], vrL[1]);
            mma_bf16(oI[0], wcH[0], viL[0]); mma_bf16(oI[1], wcH[1], viL[1]);
            mma_bf16(oR[0], nsH[0], viL[0]); mma_bf16(oR[1], nsH[1], viL[1]);
            mma_bf16(oI[0], wsH[0], vrL[0]); mma_bf16(oI[1], wsH[1], vrL[1]);
            mma_bf16(oR[0], wcL[0], vrH[0]); mma_bf16(oR[1], wcL[1], vrH[1]);
            mma_bf16(oI[0], wcL[0], viH[0]); mma_bf16(oI[1], wcL[1], viH[1]);
            mma_bf16(oR[0], nsL[0], viH[0]); mma_bf16(oR[1], nsL[1], viH[1]);
            mma_bf16(oI[0], wsL[0], vrH[0]); mma_bf16(oI[1], wsL[1], vrH[1]);
        }
        int wcol = h * 32 + 4 * w + t;          // word col in [tok][512] layout
        size_t r0w = (tok + q0 + g) * 512 + wcol;
        size_t r1w = (tok + q0 + g + 8) * 512 + wcol;
        unsigned H, L;
        split_pair(oR[0][0] + oR[1][0], oR[0][1] + oR[1][1], H, L);
        g_aoRH[r0w] = H; g_aoRL[r0w] = L;
        split_pair(oR[0][2] + oR[1][2], oR[0][3] + oR[1][3], H, L);
        g_aoRH[r1w] = H; g_aoRL[r1w] = L;
        split_pair(oI[0][0] + oI[1][0], oI[0][1] + oI[1][1], H, L);
        g_aoIH[r0w] = H; g_aoIL[r0w] = L;
        split_pair(oI[0][2] + oI[1][2], oI[0][3] + oI[1][3], H, L);
        g_aoIH[r1w] = H; g_aoIL[r1w] = L;
    }
}

// ---------------- launch ----------------
extern "C" void kernel_launch(void* const* d_in, const int* in_sizes, int n_in,
                              void* d_out, int out_size)
{
    const float* x_re    = (const float*)d_in[0];
    const float* x_im    = (const float*)d_in[1];
    const float* wqkv_re = (const float*)d_in[2];
    const float* wqkv_im = (const float*)d_in[3];
    const float* wo_re   = (const float*)d_in[4];
    const float* wo_im   = (const float*)d_in[5];
    float* out = (float*)d_out;

    float *qkv_r, *qkv_i;
    cudaGetSymbolAddress((void**)&qkv_r, g_qkv_r);
    cudaGetSymbolAddress((void**)&qkv_i, g_qkv_i);
    unsigned *xRH, *xRL, *xIH, *xIL, *wqRH, *wqRL, *wqIH, *wqIL;
    unsigned *woRH, *woRL, *woIH, *woIL, *aoRH, *aoRL, *aoIH, *aoIL;
    cudaGetSymbolAddress((void**)&xRH, g_xRH);   cudaGetSymbolAddress((void**)&xRL, g_xRL);
    cudaGetSymbolAddress((void**)&xIH, g_xIH);   cudaGetSymbolAddress((void**)&xIL, g_xIL);
    cudaGetSymbolAddress((void**)&wqRH, g_wqRH); cudaGetSymbolAddress((void**)&wqRL, g_wqRL);
    cudaGetSymbolAddress((void**)&wqIH, g_wqIH); cudaGetSymbolAddress((void**)&wqIL, g_wqIL);
    cudaGetSymbolAddress((void**)&woRH, g_woRH); cudaGetSymbolAddress((void**)&woRL, g_woRL);
    cudaGetSymbolAddress((void**)&woIH, g_woIH); cudaGetSymbolAddress((void**)&woIL, g_woIL);
    cudaGetSymbolAddress((void**)&aoRH, g_aoRH); cudaGetSymbolAddress((void**)&aoRL, g_aoRL);
    cudaGetSymbolAddress((void**)&aoIH, g_aoIH); cudaGetSymbolAddress((void**)&aoIL, g_aoIL);

    cudaFuncSetAttribute(attn_kernel,
                         cudaFuncAttributeMaxDynamicSharedMemorySize, ATTN_SMEM);

    // 1. RoPE rotor table + operand pre-splits (float4-vectorized)
    rope_table_kernel<<<S_LEN, DHEAD>>>();
    pack_kernel<<<NTOK * 256 / 256, 256>>>(x_re, xRH, xRL);
    pack_kernel<<<NTOK * 256 / 256, 256>>>(x_im, xIH, xIL);
    pack_kernel<<<D3 * 256 / 256, 256>>>(wqkv_re, wqRH, wqRL);
    pack_kernel<<<D3 * 256 / 256, 256>>>(wqkv_im, wqIH, wqIL);
    pack_kernel<<<DMODEL * 256 / 256, 256>>>(wo_re, woRH, woRL);
    pack_kernel<<<DMODEL * 256 / 256, 256>>>(wo_im, woIH, woIL);

    // 2. complex QKV projection (pre-split inputs, ILP-ordered MMAs)
    dim3 g1(D3 / 64, NTOK / 64);
    cgemm_pk_kernel<<<g1, 128>>>(xRH, xRL, xIH, xIL,
                                 wqRH, wqRL, wqIH, wqIL,
                                 qkv_r, qkv_i, D3, DMODEL / 2);

    // 3. K rotate+split and V transpose+split into MMA-ready bf16 H/L arrays
    dim3 g2(64, BH);
    kpack_kernel<<<g2, 256>>>(qkv_r, qkv_i);
    dim3 g3(S_LEN / 64, BH);
    vpack_kernel<<<g3, 256>>>(qkv_r, qkv_i);

    // 4. fused all-MMA attention, 16 q-rows per block (writes pre-split output)
    dim3 g4(S_LEN / 16, NHEAD, BATCH);
    attn_kernel<<<g4, 256, ATTN_SMEM>>>(qkv_r, qkv_i);

    // 5. complex output projection straight into d_out ([2,B,S,D])
    dim3 g5(DMODEL / 64, NTOK / 64);
    cgemm_pk_kernel<<<g5, 128>>>(aoRH, aoRL, aoIH, aoIL,
                                 woRH, woRL, woIH, woIL,
                                 out, out + (size_t)NTOK * DMODEL,
                                 DMODEL, DMODEL / 2);
}